// round 12
// baseline (speedup 1.0000x reference)
#include <cuda_runtime.h>
#include <cuda_bf16.h>
#include <mma.h>
#include <math.h>
#include <stdint.h>

using namespace nvcuda;

// Problem constants
#define NN 20000
#define NPAD 20096            // 157 * 128 padded M (padding rows never consumed)
#define EE 640000
#define GG 128
#define RR 8
#define KSPLIT 384            // [hi | hi | lo] split-K
#define NOUT1 1152
#define NOUT2 512

// ---------------- scratch (device globals; device-code use only) -----------
__device__ float g_y[(size_t)NPAD * 1024];               // ~82 MB (relations)
__device__ float g_hroot[(size_t)NPAD * GG];             // x @ root
__device__ float g_hacc[NN * GG];
__device__ __nv_bfloat16 g_split[(size_t)NPAD * KSPLIT]; // A' (x, later h)
__device__ __nv_bfloat16 g_b1[(size_t)NOUT1 * KSPLIT];
__device__ __nv_bfloat16 g_b2[(size_t)NOUT2 * KSPLIT];
__device__ float g_q[(size_t)NPAD * GG];
__device__ float g_k[(size_t)NPAD * GG];
__device__ float g_v[(size_t)NPAD * GG];
__device__ float g_s[(size_t)NPAD * GG];
__device__ float g_cnt[NN * RR];
__device__ float g_den[NN];

// ---------------- vector reduction (sm_90+ PTX, arch-generic) ---------------
__device__ __forceinline__ void red_add_v4(float* p, float a, float b,
                                           float c, float d) {
    asm volatile("red.global.add.v4.f32 [%0], {%1, %2, %3, %4};"
                 :: "l"(p), "f"(a), "f"(b), "f"(c), "f"(d) : "memory");
}

// ---------------- zero / count ----------------------------------------------
__global__ void zero_kernel(float* __restrict__ out) {
    int i = blockIdx.x * blockDim.x + threadIdx.x;
    if (i < NN * GG / 4) {
        *(float4*)&g_hacc[i * 4] = make_float4(0.f, 0.f, 0.f, 0.f);
        *(float4*)&out[i * 4]    = make_float4(0.f, 0.f, 0.f, 0.f);
    }
    if (i < NN * RR) g_cnt[i] = 0.f;
    if (i < NN) g_den[i] = 0.f;
}

__global__ void count_kernel(const int* __restrict__ dst,
                             const int* __restrict__ etype) {
    int e = blockIdx.x * blockDim.x + threadIdx.x;
    if (e >= EE) return;
    atomicAdd(&g_cnt[dst[e] * RR + etype[e]], 1.0f);
}

// ---------------- split packing ---------------------------------------------
__device__ __forceinline__ void split_write(__nv_bfloat16* row, int k, float v) {
    __nv_bfloat16 hi = __float2bfloat16(v);
    __nv_bfloat16 lo = __float2bfloat16(v - __bfloat162float(hi));
    row[k] = hi; row[GG + k] = hi; row[2 * GG + k] = lo;   // A-style [hi|hi|lo]
}
__device__ __forceinline__ void split_write_b(__nv_bfloat16* row, int k, float v) {
    __nv_bfloat16 hi = __float2bfloat16(v);
    __nv_bfloat16 lo = __float2bfloat16(v - __bfloat162float(hi));
    row[k] = hi; row[GG + k] = lo; row[2 * GG + k] = hi;   // B-style [hi|lo|hi]
}

__global__ void pack_b1_kernel(const float* __restrict__ rgcn_w,
                               const float* __restrict__ root) {
    int i = blockIdx.x * blockDim.x + threadIdx.x;
    if (i >= NOUT1 * GG) return;
    int np = i >> 7, k = i & 127;
    float v;
    if (np < 1024) {
        int r = np >> 7, n = np & 127;
        v = rgcn_w[r * 16384 + k * 128 + n];
    } else {
        v = root[k * 128 + (np - 1024)];
    }
    split_write_b(&g_b1[(size_t)np * KSPLIT], k, v);
}

__global__ void pack_b2_kernel(const float* __restrict__ Wq,
                               const float* __restrict__ Wk,
                               const float* __restrict__ Wv,
                               const float* __restrict__ Ws) {
    int i = blockIdx.x * blockDim.x + threadIdx.x;
    if (i >= NOUT2 * GG) return;
    int np = i >> 7, k = i & 127;
    int sel = np >> 7, n = np & 127;
    const float* W = (sel == 0) ? Wq : (sel == 1) ? Wk : (sel == 2) ? Wv : Ws;
    split_write_b(&g_b2[(size_t)np * KSPLIT], k, W[k * 128 + n]);
}

__global__ void split_x_kernel(const float* __restrict__ x) {
    int i = blockIdx.x * blockDim.x + threadIdx.x;
    if (i >= NN * GG) return;
    int m = i >> 7, k = i & 127;
    split_write(&g_split[(size_t)m * KSPLIT], k, x[i]);
}

// ---------------- WMMA bf16 GEMM: 128x128 block tile, BK=32 (proven R8) -----
__global__ void __launch_bounds__(256)
gemm_wmma_kernel(int mode) {
    __shared__ __nv_bfloat16 As[128][40];
    __shared__ __nv_bfloat16 Bs[128][40];
    int tid = threadIdx.x;
    int warp = tid >> 5;
    int wm = warp >> 1, wn = warp & 1;
    int row0 = blockIdx.x * 128;
    int n0 = blockIdx.y * 128;
    const __nv_bfloat16* Bgm = (mode == 0) ? g_b1 : g_b2;

    wmma::fragment<wmma::accumulator, 16, 16, 16, float> acc[2][4];
    #pragma unroll
    for (int i = 0; i < 2; i++)
        #pragma unroll
        for (int j = 0; j < 4; j++) wmma::fill_fragment(acc[i][j], 0.f);

    for (int k0 = 0; k0 < KSPLIT; k0 += 32) {
        #pragma unroll
        for (int i = 0; i < 2; i++) {
            int idx = tid + i * 256;
            int r = idx >> 2;
            int kc = (idx & 3) * 8;
            *(uint4*)&As[r][kc] =
                *(const uint4*)&g_split[(size_t)(row0 + r) * KSPLIT + k0 + kc];
            *(uint4*)&Bs[r][kc] =
                *(const uint4*)&Bgm[(size_t)(n0 + r) * KSPLIT + k0 + kc];
        }
        __syncthreads();
        #pragma unroll
        for (int ks = 0; ks < 32; ks += 16) {
            wmma::fragment<wmma::matrix_a, 16, 16, 16, __nv_bfloat16, wmma::row_major> af[2];
            wmma::fragment<wmma::matrix_b, 16, 16, 16, __nv_bfloat16, wmma::col_major> bf[4];
            #pragma unroll
            for (int i = 0; i < 2; i++)
                wmma::load_matrix_sync(af[i], &As[wm * 32 + i * 16][ks], 40);
            #pragma unroll
            for (int j = 0; j < 4; j++)
                wmma::load_matrix_sync(bf[j], &Bs[wn * 64 + j * 16][ks], 40);
            #pragma unroll
            for (int i = 0; i < 2; i++)
                #pragma unroll
                for (int j = 0; j < 4; j++)
                    wmma::mma_sync(acc[i][j], af[i], bf[j], acc[i][j]);
        }
        __syncthreads();
    }

    if (mode == 0) {
        if (blockIdx.y < 8) {
            #pragma unroll
            for (int i = 0; i < 2; i++)
                #pragma unroll
                for (int j = 0; j < 4; j++)
                    wmma::store_matrix_sync(
                        &g_y[(size_t)(row0 + wm * 32 + i * 16) * 1024
                             + n0 + wn * 64 + j * 16],
                        acc[i][j], 1024, wmma::mem_row_major);
        } else {
            #pragma unroll
            for (int i = 0; i < 2; i++)
                #pragma unroll
                for (int j = 0; j < 4; j++)
                    wmma::store_matrix_sync(
                        &g_hroot[(size_t)(row0 + wm * 32 + i * 16) * GG
                                 + wn * 64 + j * 16],
                        acc[i][j], GG, wmma::mem_row_major);
        }
    } else {
        int seg = blockIdx.y;
        float* Cb = (seg == 0) ? g_q : (seg == 1) ? g_k : (seg == 2) ? g_v : g_s;
        #pragma unroll
        for (int i = 0; i < 2; i++)
            #pragma unroll
            for (int j = 0; j < 4; j++)
                wmma::store_matrix_sync(
                    &Cb[(size_t)(row0 + wm * 32 + i * 16) * GG + wn * 64 + j * 16],
                    acc[i][j], GG, wmma::mem_row_major);
    }
}

// ---------------- scatter: hacc[dst] += y[src, et*128..]/cnt ----------------
// 4 edges per warp, batched index loads -> 4 independent gathers in flight.
// EE / (4*8) = 20000 blocks exactly; no bounds checks.
__global__ void scatter_y_kernel(const int* __restrict__ src,
                                 const int* __restrict__ dst,
                                 const int* __restrict__ etype) {
    int e0 = (blockIdx.x * 8 + (threadIdx.x >> 5)) * 4;
    int lane = threadIdx.x & 31;
    int s[4], d[4], r[4];
    #pragma unroll
    for (int u = 0; u < 4; u++) {
        s[u] = __ldg(&src[e0 + u]);
        d[u] = __ldg(&dst[e0 + u]);
        r[u] = __ldg(&etype[e0 + u]);
    }
    float inv[4];
    #pragma unroll
    for (int u = 0; u < 4; u++)
        inv[u] = 1.0f / fmaxf(g_cnt[d[u] * RR + r[u]], 1.0f);
    float4 yv[4];
    #pragma unroll
    for (int u = 0; u < 4; u++)
        yv[u] = *(const float4*)&g_y[(size_t)s[u] * 1024 + r[u] * 128 + lane * 4];
    #pragma unroll
    for (int u = 0; u < 4; u++)
        red_add_v4(&g_hacc[d[u] * GG + lane * 4],
                   yv[u].x * inv[u], yv[u].y * inv[u],
                   yv[u].z * inv[u], yv[u].w * inv[u]);
}

// h = relu(hacc + hroot + bias); write split(h) into g_split for GEMM2
__global__ void finalize_split_kernel(const float* __restrict__ bias) {
    int i = blockIdx.x * blockDim.x + threadIdx.x;
    if (i >= NN * GG) return;
    int m = i >> 7, c = i & 127;
    float h = g_hacc[i] + g_hroot[(size_t)m * GG + c] + bias[c];
    h = fmaxf(h, 0.f);
    split_write(&g_split[(size_t)m * KSPLIT], c, h);
}

// ---------------- fused attention edge pass ---------------------------------
// Half-warp (16 lanes) per edge; each lane covers 8 features (2 x float4).
// e = exp(((q[d]+bq).(k[s]+bk))/sqrt(128)); den[d] += e; out[d] += e*(v[s]+bv)
// EE / 16 = 40000 blocks exactly; no bounds checks.
__global__ void edge_attn_kernel(const int* __restrict__ src,
                                 const int* __restrict__ dst,
                                 const float* __restrict__ bq,
                                 const float* __restrict__ bk,
                                 const float* __restrict__ bv,
                                 float* __restrict__ out) {
    int e = blockIdx.x * 16 + (threadIdx.x >> 4);
    int l16 = threadIdx.x & 15;
    int c0 = l16 * 8;
    int s = __ldg(&src[e]), d = __ldg(&dst[e]);
    const float* qp = &g_q[(size_t)d * GG + c0];
    const float* kp = &g_k[(size_t)s * GG + c0];
    float4 q0 = *(const float4*)qp;
    float4 q1 = *(const float4*)(qp + 4);
    float4 k0 = *(const float4*)kp;
    float4 k1 = *(const float4*)(kp + 4);
    float4 bq0 = *(const float4*)&bq[c0];
    float4 bq1 = *(const float4*)&bq[c0 + 4];
    float4 bk0 = *(const float4*)&bk[c0];
    float4 bk1 = *(const float4*)&bk[c0 + 4];
    float acc = (q0.x + bq0.x) * (k0.x + bk0.x)
              + (q0.y + bq0.y) * (k0.y + bk0.y)
              + (q0.z + bq0.z) * (k0.z + bk0.z)
              + (q0.w + bq0.w) * (k0.w + bk0.w)
              + (q1.x + bq1.x) * (k1.x + bk1.x)
              + (q1.y + bq1.y) * (k1.y + bk1.y)
              + (q1.z + bq1.z) * (k1.z + bk1.z)
              + (q1.w + bq1.w) * (k1.w + bk1.w);
    #pragma unroll
    for (int o = 8; o; o >>= 1) acc += __shfl_xor_sync(0xFFFFFFFFu, acc, o);
    float ex = __expf(acc * 0.08838834764831845f);  // 1/sqrt(128)
    if (l16 == 0) atomicAdd(&g_den[d], ex);
    const float* vp = &g_v[(size_t)s * GG + c0];
    float4 v0 = *(const float4*)vp;
    float4 v1 = *(const float4*)(vp + 4);
    float4 bv0 = *(const float4*)&bv[c0];
    float4 bv1 = *(const float4*)&bv[c0 + 4];
    float* od = out + (size_t)d * GG + c0;
    red_add_v4(od, ex * (v0.x + bv0.x), ex * (v0.y + bv0.y),
               ex * (v0.z + bv0.z), ex * (v0.w + bv0.w));
    red_add_v4(od + 4, ex * (v1.x + bv1.x), ex * (v1.y + bv1.y),
               ex * (v1.z + bv1.z), ex * (v1.w + bv1.w));
}

// out = relu(attn_num/den + skip + bs)
__global__ void final_kernel(float* __restrict__ out,
                             const float* __restrict__ bs) {
    int i = blockIdx.x * blockDim.x + threadIdx.x;
    if (i >= NN * GG) return;
    int m = i >> 7, c = i & 127;
    float invden = 1.0f / fmaxf(g_den[m], 1e-16f);
    out[i] = fmaxf(out[i] * invden + g_s[(size_t)m * GG + c] + bs[c], 0.f);
}

// ---------------------------------------------------------------------------
extern "C" void kernel_launch(void* const* d_in, const int* in_sizes, int n_in,
                              void* d_out, int out_size) {
    const float* x        = (const float*)d_in[0];
    const int* edge_index = (const int*)d_in[1];   // [2, E]: src then dst
    const int* etype      = (const int*)d_in[2];
    const float* rgcn_w   = (const float*)d_in[3];
    const float* rgcn_root= (const float*)d_in[4];
    const float* rgcn_b   = (const float*)d_in[5];
    const float* Wq = (const float*)d_in[6];  const float* bq = (const float*)d_in[7];
    const float* Wk = (const float*)d_in[8];  const float* bk = (const float*)d_in[9];
    const float* Wv = (const float*)d_in[10]; const float* bv = (const float*)d_in[11];
    const float* Ws = (const float*)d_in[12]; const float* bs = (const float*)d_in[13];
    float* out = (float*)d_out;

    const int* src = edge_index;
    const int* dst = edge_index + EE;

    // 0-2: packs + split
    pack_b1_kernel<<<(NOUT1 * GG + 255) / 256, 256>>>(rgcn_w, rgcn_root);
    pack_b2_kernel<<<(NOUT2 * GG + 255) / 256, 256>>>(Wq, Wk, Wv, Ws);
    split_x_kernel<<<(NN * GG + 255) / 256, 256>>>(x);
    // 3 (ncu capture slot): y = x @ [W_r | root]
    {
        dim3 g(NPAD / 128, 9);
        gemm_wmma_kernel<<<g, 256>>>(0);
    }
    // 4: zero hacc/out/cnt/den
    zero_kernel<<<(NN * GG / 4 + 255) / 256, 256>>>(out);
    // 5: per-(dst,rel) counts
    count_kernel<<<(EE + 255) / 256, 256>>>(dst, etype);
    // 6: aggregate transformed features (4 edges/warp, MLP=4)
    scatter_y_kernel<<<EE / 32, 256>>>(src, dst, etype);
    // 7: h = relu(hacc + hroot + bias), split into g_split
    finalize_split_kernel<<<(NN * GG + 255) / 256, 256>>>(rgcn_b);
    // 8: q,k,v,skip = h @ [Wq|Wk|Wv|Ws]
    {
        dim3 g(NPAD / 128, 4);
        gemm_wmma_kernel<<<g, 256>>>(1);
    }
    // 9: fused attention edge pass (half-warp per edge)
    edge_attn_kernel<<<EE / 16, 256>>>(src, dst, bq, bk, bv, out);
    // 10: out = relu(out/den + skip + bs)
    final_kernel<<<(NN * GG + 255) / 256, 256>>>(out, bs);
}

// round 13
// speedup vs baseline: 1.2010x; 1.2010x over previous
#include <cuda_runtime.h>
#include <cuda_bf16.h>
#include <mma.h>
#include <math.h>
#include <stdint.h>

using namespace nvcuda;

// Problem constants
#define NN 20000
#define NPAD 20096            // 157 * 128 padded M (padding rows never consumed)
#define EE 640000
#define GG 128
#define RR 8
#define KSPLIT 384            // [hi | hi | lo] split-K
#define NOUT1 1152
#define NOUT2 512
#define NB 79                 // ceil(NN/256) scan blocks

// ---------------- scratch (device globals; device-code use only) -----------
__device__ float g_y[(size_t)NPAD * 1024];               // ~82 MB (relations)
__device__ float g_hroot[(size_t)NPAD * GG];             // x @ root
__device__ __nv_bfloat16 g_split[(size_t)NPAD * KSPLIT]; // A' (x, later h)
__device__ __nv_bfloat16 g_b1[(size_t)NOUT1 * KSPLIT];
__device__ __nv_bfloat16 g_b2[(size_t)NOUT2 * KSPLIT];
__device__ float g_q[(size_t)NPAD * GG];
__device__ float g_k[(size_t)NPAD * GG];
__device__ float g_v[(size_t)NPAD * GG];
__device__ float g_s[(size_t)NPAD * GG];
__device__ int g_deg[NN];
__device__ int g_cur[NN];
__device__ int g_off[NN + 1];
__device__ int g_bsum[NB];
__device__ int g_eid[EE];

// ---------------- CSR build -------------------------------------------------
__global__ void init_kernel() {
    int i = blockIdx.x * blockDim.x + threadIdx.x;
    if (i < NN) { g_deg[i] = 0; g_cur[i] = 0; }
}

__global__ void deg_kernel(const int* __restrict__ dst) {
    int e = blockIdx.x * blockDim.x + threadIdx.x;
    if (e < EE) atomicAdd(&g_deg[dst[e]], 1);
}

__global__ void scan1_kernel() {
    __shared__ int sh[256];
    int tid = threadIdx.x;
    int i = blockIdx.x * 256 + tid;
    sh[tid] = (i < NN) ? g_deg[i] : 0;
    __syncthreads();
    #pragma unroll
    for (int o = 1; o < 256; o <<= 1) {
        int t = (tid >= o) ? sh[tid - o] : 0;
        __syncthreads();
        sh[tid] += t;
        __syncthreads();
    }
    if (i < NN) g_off[i + 1] = sh[tid];
    if (tid == 255) g_bsum[blockIdx.x] = sh[255];
}

__global__ void scan2_kernel() {
    if (threadIdx.x == 0) {
        int acc = 0;
        for (int b = 0; b < NB; b++) {
            int t = g_bsum[b];
            g_bsum[b] = acc;
            acc += t;
        }
        g_off[0] = 0;
    }
}

__global__ void scan3_kernel() {
    int i = blockIdx.x * blockDim.x + threadIdx.x;
    if (i < NN) g_off[i + 1] += g_bsum[i >> 8];
}

__global__ void fill_kernel(const int* __restrict__ dst) {
    int e = blockIdx.x * blockDim.x + threadIdx.x;
    if (e >= EE) return;
    int d = dst[e];
    int p = atomicAdd(&g_cur[d], 1);
    g_eid[g_off[d] + p] = e;
}

// ---------------- split packing ---------------------------------------------
__device__ __forceinline__ void split_write(__nv_bfloat16* row, int k, float v) {
    __nv_bfloat16 hi = __float2bfloat16(v);
    __nv_bfloat16 lo = __float2bfloat16(v - __bfloat162float(hi));
    row[k] = hi; row[GG + k] = hi; row[2 * GG + k] = lo;   // A-style [hi|hi|lo]
}
__device__ __forceinline__ void split_write_b(__nv_bfloat16* row, int k, float v) {
    __nv_bfloat16 hi = __float2bfloat16(v);
    __nv_bfloat16 lo = __float2bfloat16(v - __bfloat162float(hi));
    row[k] = hi; row[GG + k] = lo; row[2 * GG + k] = hi;   // B-style [hi|lo|hi]
}

__global__ void pack_b1_kernel(const float* __restrict__ rgcn_w,
                               const float* __restrict__ root) {
    int i = blockIdx.x * blockDim.x + threadIdx.x;
    if (i >= NOUT1 * GG) return;
    int np = i >> 7, k = i & 127;
    float v;
    if (np < 1024) {
        int r = np >> 7, n = np & 127;
        v = rgcn_w[r * 16384 + k * 128 + n];
    } else {
        v = root[k * 128 + (np - 1024)];
    }
    split_write_b(&g_b1[(size_t)np * KSPLIT], k, v);
}

__global__ void pack_b2_kernel(const float* __restrict__ Wq,
                               const float* __restrict__ Wk,
                               const float* __restrict__ Wv,
                               const float* __restrict__ Ws) {
    int i = blockIdx.x * blockDim.x + threadIdx.x;
    if (i >= NOUT2 * GG) return;
    int np = i >> 7, k = i & 127;
    int sel = np >> 7, n = np & 127;
    const float* W = (sel == 0) ? Wq : (sel == 1) ? Wk : (sel == 2) ? Wv : Ws;
    split_write_b(&g_b2[(size_t)np * KSPLIT], k, W[k * 128 + n]);
}

__global__ void split_x_kernel(const float* __restrict__ x) {
    int i = blockIdx.x * blockDim.x + threadIdx.x;
    if (i >= NN * GG) return;
    int m = i >> 7, k = i & 127;
    split_write(&g_split[(size_t)m * KSPLIT], k, x[i]);
}

// ---------------- WMMA bf16 GEMM: 128x128 block tile, BK=32 (proven R8) -----
__global__ void __launch_bounds__(256)
gemm_wmma_kernel(int mode) {
    __shared__ __nv_bfloat16 As[128][40];
    __shared__ __nv_bfloat16 Bs[128][40];
    int tid = threadIdx.x;
    int warp = tid >> 5;
    int wm = warp >> 1, wn = warp & 1;
    int row0 = blockIdx.x * 128;
    int n0 = blockIdx.y * 128;
    const __nv_bfloat16* Bgm = (mode == 0) ? g_b1 : g_b2;

    wmma::fragment<wmma::accumulator, 16, 16, 16, float> acc[2][4];
    #pragma unroll
    for (int i = 0; i < 2; i++)
        #pragma unroll
        for (int j = 0; j < 4; j++) wmma::fill_fragment(acc[i][j], 0.f);

    for (int k0 = 0; k0 < KSPLIT; k0 += 32) {
        #pragma unroll
        for (int i = 0; i < 2; i++) {
            int idx = tid + i * 256;
            int r = idx >> 2;
            int kc = (idx & 3) * 8;
            *(uint4*)&As[r][kc] =
                *(const uint4*)&g_split[(size_t)(row0 + r) * KSPLIT + k0 + kc];
            *(uint4*)&Bs[r][kc] =
                *(const uint4*)&Bgm[(size_t)(n0 + r) * KSPLIT + k0 + kc];
        }
        __syncthreads();
        #pragma unroll
        for (int ks = 0; ks < 32; ks += 16) {
            wmma::fragment<wmma::matrix_a, 16, 16, 16, __nv_bfloat16, wmma::row_major> af[2];
            wmma::fragment<wmma::matrix_b, 16, 16, 16, __nv_bfloat16, wmma::col_major> bf[4];
            #pragma unroll
            for (int i = 0; i < 2; i++)
                wmma::load_matrix_sync(af[i], &As[wm * 32 + i * 16][ks], 40);
            #pragma unroll
            for (int j = 0; j < 4; j++)
                wmma::load_matrix_sync(bf[j], &Bs[wn * 64 + j * 16][ks], 40);
            #pragma unroll
            for (int i = 0; i < 2; i++)
                #pragma unroll
                for (int j = 0; j < 4; j++)
                    wmma::mma_sync(acc[i][j], af[i], bf[j], acc[i][j]);
        }
        __syncthreads();
    }

    if (mode == 0) {
        if (blockIdx.y < 8) {
            #pragma unroll
            for (int i = 0; i < 2; i++)
                #pragma unroll
                for (int j = 0; j < 4; j++)
                    wmma::store_matrix_sync(
                        &g_y[(size_t)(row0 + wm * 32 + i * 16) * 1024
                             + n0 + wn * 64 + j * 16],
                        acc[i][j], 1024, wmma::mem_row_major);
        } else {
            #pragma unroll
            for (int i = 0; i < 2; i++)
                #pragma unroll
                for (int j = 0; j < 4; j++)
                    wmma::store_matrix_sync(
                        &g_hroot[(size_t)(row0 + wm * 32 + i * 16) * GG
                                 + wn * 64 + j * 16],
                        acc[i][j], GG, wmma::mem_row_major);
        }
    } else {
        int seg = blockIdx.y;
        float* Cb = (seg == 0) ? g_q : (seg == 1) ? g_k : (seg == 2) ? g_v : g_s;
        #pragma unroll
        for (int i = 0; i < 2; i++)
            #pragma unroll
            for (int j = 0; j < 4; j++)
                wmma::store_matrix_sync(
                    &Cb[(size_t)(row0 + wm * 32 + i * 16) * GG + wn * 64 + j * 16],
                    acc[i][j], GG, wmma::mem_row_major);
    }
}

// ---------------- RGCN aggregation: warp per dst, register accumulation -----
// pass 1: per-relation edge counts (uniform, packed 8-bit counters)
// pass 2: acc += y[src, r*128..] * inv[r]; then h=relu(acc+hroot+bias) -> split
__global__ void __launch_bounds__(256)
rgcn_agg_kernel(const int* __restrict__ src,
                const int* __restrict__ et,
                const float* __restrict__ bias) {
    __shared__ float sh_inv[8][8];
    int warp = threadIdx.x >> 5;
    int lane = threadIdx.x & 31;
    int node = blockIdx.x * 8 + warp;
    if (node >= NN) return;
    int beg = g_off[node], end = g_off[node + 1];

    // pass 1: counts per relation (uniform across warp; 8-bit packed)
    unsigned cp0 = 0, cp1 = 0;
    for (int i = beg; i < end; i++) {
        int e = __ldg(&g_eid[i]);
        int r = __ldg(&et[e]);
        if (r < 4) cp0 += 1u << (r * 8);
        else       cp1 += 1u << ((r - 4) * 8);
    }
    if (lane < 8) {
        unsigned c = (lane < 4) ? ((cp0 >> (lane * 8)) & 255u)
                                : ((cp1 >> ((lane - 4) * 8)) & 255u);
        sh_inv[warp][lane] = 1.0f / fmaxf((float)c, 1.0f);
    }
    __syncwarp();

    // pass 2: gather + accumulate
    float4 a = make_float4(0.f, 0.f, 0.f, 0.f);
    for (int i = beg; i < end; i++) {
        int e = __ldg(&g_eid[i]);
        int s = __ldg(&src[e]);
        int r = __ldg(&et[e]);
        float inv = sh_inv[warp][r];
        float4 yv = *(const float4*)&g_y[(size_t)s * 1024 + r * 128 + lane * 4];
        a.x += yv.x * inv; a.y += yv.y * inv;
        a.z += yv.z * inv; a.w += yv.w * inv;
    }

    int c0 = lane * 4;
    const float* hr = &g_hroot[(size_t)node * GG + c0];
    float h0 = fmaxf(a.x + hr[0] + bias[c0 + 0], 0.f);
    float h1 = fmaxf(a.y + hr[1] + bias[c0 + 1], 0.f);
    float h2 = fmaxf(a.z + hr[2] + bias[c0 + 2], 0.f);
    float h3 = fmaxf(a.w + hr[3] + bias[c0 + 3], 0.f);
    __nv_bfloat16* row = &g_split[(size_t)node * KSPLIT];
    split_write(row, c0 + 0, h0);
    split_write(row, c0 + 1, h1);
    split_write(row, c0 + 2, h2);
    split_write(row, c0 + 3, h3);
}

// ---------------- attention: warp per dst, register num/den -----------------
// out[d] = relu( (sum_e ex_e * (v[s_e]+bv)) / (sum_e ex_e) + skip[d] + bs )
__global__ void __launch_bounds__(256)
edge_attn_kernel(const int* __restrict__ src,
                 const float* __restrict__ bq,
                 const float* __restrict__ bk,
                 const float* __restrict__ bv,
                 const float* __restrict__ bs,
                 float* __restrict__ out) {
    int warp = threadIdx.x >> 5;
    int lane = threadIdx.x & 31;
    int node = blockIdx.x * 8 + warp;
    if (node >= NN) return;
    (void)warp;
    int beg = g_off[node], end = g_off[node + 1];
    int c0 = lane * 4;

    float4 bq4 = *(const float4*)&bq[c0];
    float4 bk4 = *(const float4*)&bk[c0];
    float4 bv4 = *(const float4*)&bv[c0];
    float4 q4 = *(const float4*)&g_q[(size_t)node * GG + c0];
    q4.x += bq4.x; q4.y += bq4.y; q4.z += bq4.z; q4.w += bq4.w;

    float4 num = make_float4(0.f, 0.f, 0.f, 0.f);
    float den = 0.f;
    for (int i = beg; i < end; i++) {
        int e = __ldg(&g_eid[i]);
        int s = __ldg(&src[e]);
        float4 k4 = *(const float4*)&g_k[(size_t)s * GG + c0];
        float d = q4.x * (k4.x + bk4.x) + q4.y * (k4.y + bk4.y)
                + q4.z * (k4.z + bk4.z) + q4.w * (k4.w + bk4.w);
        #pragma unroll
        for (int o = 16; o; o >>= 1) d += __shfl_xor_sync(0xFFFFFFFFu, d, o);
        float ex = __expf(d * 0.08838834764831845f);  // 1/sqrt(128)
        den += ex;
        float4 v4 = *(const float4*)&g_v[(size_t)s * GG + c0];
        num.x += ex * (v4.x + bv4.x);
        num.y += ex * (v4.y + bv4.y);
        num.z += ex * (v4.z + bv4.z);
        num.w += ex * (v4.w + bv4.w);
    }
    float invden = 1.0f / fmaxf(den, 1e-16f);
    const float* sp = &g_s[(size_t)node * GG + c0];
    float4 bs4 = *(const float4*)&bs[c0];
    float4 o4;
    o4.x = fmaxf(num.x * invden + sp[0] + bs4.x, 0.f);
    o4.y = fmaxf(num.y * invden + sp[1] + bs4.y, 0.f);
    o4.z = fmaxf(num.z * invden + sp[2] + bs4.z, 0.f);
    o4.w = fmaxf(num.w * invden + sp[3] + bs4.w, 0.f);
    *(float4*)&out[(size_t)node * GG + c0] = o4;
}

// ---------------------------------------------------------------------------
extern "C" void kernel_launch(void* const* d_in, const int* in_sizes, int n_in,
                              void* d_out, int out_size) {
    const float* x        = (const float*)d_in[0];
    const int* edge_index = (const int*)d_in[1];   // [2, E]: src then dst
    const int* etype      = (const int*)d_in[2];
    const float* rgcn_w   = (const float*)d_in[3];
    const float* rgcn_root= (const float*)d_in[4];
    const float* rgcn_b   = (const float*)d_in[5];
    const float* Wq = (const float*)d_in[6];  const float* bq = (const float*)d_in[7];
    const float* Wk = (const float*)d_in[8];  const float* bk = (const float*)d_in[9];
    const float* Wv = (const float*)d_in[10]; const float* bv = (const float*)d_in[11];
    const float* Ws = (const float*)d_in[12]; const float* bs = (const float*)d_in[13];
    float* out = (float*)d_out;

    const int* src = edge_index;
    const int* dst = edge_index + EE;

    // 0-2: packs + split
    pack_b1_kernel<<<(NOUT1 * GG + 255) / 256, 256>>>(rgcn_w, rgcn_root);
    pack_b2_kernel<<<(NOUT2 * GG + 255) / 256, 256>>>(Wq, Wk, Wv, Ws);
    split_x_kernel<<<(NN * GG + 255) / 256, 256>>>(x);
    // 3 (ncu capture slot): y = x @ [W_r | root]
    {
        dim3 g(NPAD / 128, 9);
        gemm_wmma_kernel<<<g, 256>>>(0);
    }
    // 4-9: CSR build
    init_kernel<<<(NN + 255) / 256, 256>>>();
    deg_kernel<<<(EE + 255) / 256, 256>>>(dst);
    scan1_kernel<<<NB, 256>>>();
    scan2_kernel<<<1, 32>>>();
    scan3_kernel<<<(NN + 255) / 256, 256>>>();
    fill_kernel<<<(EE + 255) / 256, 256>>>(dst);
    // 10: RGCN aggregation (warp/dst, register acc) -> g_split
    rgcn_agg_kernel<<<(NN + 7) / 8, 256>>>(src, etype, rgcn_b);
    // 11: q,k,v,skip = h @ [Wq|Wk|Wv|Ws]
    {
        dim3 g(NPAD / 128, 4);
        gemm_wmma_kernel<<<g, 256>>>(1);
    }
    // 12: attention (warp/dst, register num/den) -> out (final)
    edge_attn_kernel<<<(NN + 7) / 8, 256>>>(src, bq, bk, bv, bs, out);
}

// round 15
// speedup vs baseline: 1.2703x; 1.0577x over previous
#include <cuda_runtime.h>
#include <cuda_bf16.h>
#include <cuda_fp16.h>
#include <mma.h>
#include <math.h>
#include <stdint.h>

using namespace nvcuda;

// Problem constants
#define NN 20000
#define NPAD 20096            // 157 * 128 padded M (padding rows never consumed)
#define EE 640000
#define GG 128
#define RR 8
#define KSPLIT 384            // [hi | hi | lo] split-K
#define NOUT1 1152
#define NOUT2 512
#define NB 79                 // ceil(NN/256) scan blocks

// ---------------- scratch (device globals; device-code use only) -----------
__device__ __half g_y[(size_t)NPAD * 1024];              // ~41 MB (relations, fp16)
__device__ float g_hroot[(size_t)NPAD * GG];             // x @ root
__device__ __nv_bfloat16 g_split[(size_t)NPAD * KSPLIT]; // A' (x, later h)
__device__ __nv_bfloat16 g_b1[(size_t)NOUT1 * KSPLIT];
__device__ __nv_bfloat16 g_b2[(size_t)NOUT2 * KSPLIT];
__device__ float g_q[(size_t)NPAD * GG];
__device__ float g_k[(size_t)NPAD * GG];
__device__ float g_v[(size_t)NPAD * GG];
__device__ float g_s[(size_t)NPAD * GG];
__device__ int g_deg[NN];
__device__ int g_cur[NN];
__device__ int g_off[NN + 1];
__device__ int g_bsum[NB];
__device__ int g_eid[EE];

// ---------------- CSR build -------------------------------------------------
__global__ void init_kernel() {
    int i = blockIdx.x * blockDim.x + threadIdx.x;
    if (i < NN) { g_deg[i] = 0; g_cur[i] = 0; }
}

__global__ void deg_kernel(const int* __restrict__ dst) {
    int e = blockIdx.x * blockDim.x + threadIdx.x;
    if (e < EE) atomicAdd(&g_deg[dst[e]], 1);
}

__global__ void scan1_kernel() {
    __shared__ int sh[256];
    int tid = threadIdx.x;
    int i = blockIdx.x * 256 + tid;
    sh[tid] = (i < NN) ? g_deg[i] : 0;
    __syncthreads();
    #pragma unroll
    for (int o = 1; o < 256; o <<= 1) {
        int t = (tid >= o) ? sh[tid - o] : 0;
        __syncthreads();
        sh[tid] += t;
        __syncthreads();
    }
    if (i < NN) g_off[i + 1] = sh[tid];
    if (tid == 255) g_bsum[blockIdx.x] = sh[255];
}

// warp-parallel exclusive scan over NB block sums
__global__ void scan2_kernel() {
    int lane = threadIdx.x;
    int carry = 0;
    for (int base = 0; base < NB; base += 32) {
        int i = base + lane;
        int orig = (i < NB) ? g_bsum[i] : 0;
        int v = orig;
        #pragma unroll
        for (int o = 1; o < 32; o <<= 1) {
            int t = __shfl_up_sync(0xFFFFFFFFu, v, o);
            if (lane >= o) v += t;
        }
        if (i < NB) g_bsum[i] = carry + v - orig;   // exclusive prefix
        carry += __shfl_sync(0xFFFFFFFFu, v, 31);
    }
    if (lane == 0) g_off[0] = 0;
}

__global__ void scan3_kernel() {
    int i = blockIdx.x * blockDim.x + threadIdx.x;
    if (i < NN) g_off[i + 1] += g_bsum[i >> 8];
}

__global__ void fill_kernel(const int* __restrict__ dst) {
    int e = blockIdx.x * blockDim.x + threadIdx.x;
    if (e >= EE) return;
    int d = dst[e];
    int p = atomicAdd(&g_cur[d], 1);
    g_eid[g_off[d] + p] = e;
}

// ---------------- split packing ---------------------------------------------
__device__ __forceinline__ void split_write(__nv_bfloat16* row, int k, float v) {
    __nv_bfloat16 hi = __float2bfloat16(v);
    __nv_bfloat16 lo = __float2bfloat16(v - __bfloat162float(hi));
    row[k] = hi; row[GG + k] = hi; row[2 * GG + k] = lo;   // A-style [hi|hi|lo]
}
__device__ __forceinline__ void split_write_b(__nv_bfloat16* row, int k, float v) {
    __nv_bfloat16 hi = __float2bfloat16(v);
    __nv_bfloat16 lo = __float2bfloat16(v - __bfloat162float(hi));
    row[k] = hi; row[GG + k] = lo; row[2 * GG + k] = hi;   // B-style [hi|lo|hi]
}

__global__ void pack_b1_kernel(const float* __restrict__ rgcn_w,
                               const float* __restrict__ root) {
    int i = blockIdx.x * blockDim.x + threadIdx.x;
    if (i >= NOUT1 * GG) return;
    int np = i >> 7, k = i & 127;
    float v;
    if (np < 1024) {
        int r = np >> 7, n = np & 127;
        v = rgcn_w[r * 16384 + k * 128 + n];
    } else {
        v = root[k * 128 + (np - 1024)];
    }
    split_write_b(&g_b1[(size_t)np * KSPLIT], k, v);
}

__global__ void pack_b2_kernel(const float* __restrict__ Wq,
                               const float* __restrict__ Wk,
                               const float* __restrict__ Wv,
                               const float* __restrict__ Ws) {
    int i = blockIdx.x * blockDim.x + threadIdx.x;
    if (i >= NOUT2 * GG) return;
    int np = i >> 7, k = i & 127;
    int sel = np >> 7, n = np & 127;
    const float* W = (sel == 0) ? Wq : (sel == 1) ? Wk : (sel == 2) ? Wv : Ws;
    split_write_b(&g_b2[(size_t)np * KSPLIT], k, W[k * 128 + n]);
}

__global__ void split_x_kernel(const float* __restrict__ x) {
    int i = blockIdx.x * blockDim.x + threadIdx.x;
    if (i >= NN * GG) return;
    int m = i >> 7, k = i & 127;
    split_write(&g_split[(size_t)m * KSPLIT], k, x[i]);
}

// ---------------- WMMA bf16 GEMM: 128x128 block tile, BK=32 (proven R8) -----
// mode 0, blockIdx.y<8: y tiles -> fp16 via smem-staged epilogue (ldm=20,
// multiple of 4 as WMMA requires for float accumulators).
__global__ void __launch_bounds__(256)
gemm_wmma_kernel(int mode) {
    __shared__ __nv_bfloat16 As[128][40];
    __shared__ __nv_bfloat16 Bs[128][40];
    __shared__ float st[8][16][20];    // per-warp 16x16 staging, pitch 20
    int tid = threadIdx.x;
    int warp = tid >> 5;
    int lane = tid & 31;
    int wm = warp >> 1, wn = warp & 1;
    int row0 = blockIdx.x * 128;
    int n0 = blockIdx.y * 128;
    const __nv_bfloat16* Bgm = (mode == 0) ? g_b1 : g_b2;

    wmma::fragment<wmma::accumulator, 16, 16, 16, float> acc[2][4];
    #pragma unroll
    for (int i = 0; i < 2; i++)
        #pragma unroll
        for (int j = 0; j < 4; j++) wmma::fill_fragment(acc[i][j], 0.f);

    for (int k0 = 0; k0 < KSPLIT; k0 += 32) {
        #pragma unroll
        for (int i = 0; i < 2; i++) {
            int idx = tid + i * 256;
            int r = idx >> 2;
            int kc = (idx & 3) * 8;
            *(uint4*)&As[r][kc] =
                *(const uint4*)&g_split[(size_t)(row0 + r) * KSPLIT + k0 + kc];
            *(uint4*)&Bs[r][kc] =
                *(const uint4*)&Bgm[(size_t)(n0 + r) * KSPLIT + k0 + kc];
        }
        __syncthreads();
        #pragma unroll
        for (int ks = 0; ks < 32; ks += 16) {
            wmma::fragment<wmma::matrix_a, 16, 16, 16, __nv_bfloat16, wmma::row_major> af[2];
            wmma::fragment<wmma::matrix_b, 16, 16, 16, __nv_bfloat16, wmma::col_major> bf[4];
            #pragma unroll
            for (int i = 0; i < 2; i++)
                wmma::load_matrix_sync(af[i], &As[wm * 32 + i * 16][ks], 40);
            #pragma unroll
            for (int j = 0; j < 4; j++)
                wmma::load_matrix_sync(bf[j], &Bs[wn * 64 + j * 16][ks], 40);
            #pragma unroll
            for (int i = 0; i < 2; i++)
                #pragma unroll
                for (int j = 0; j < 4; j++)
                    wmma::mma_sync(acc[i][j], af[i], bf[j], acc[i][j]);
        }
        __syncthreads();
    }

    if (mode == 0) {
        if (blockIdx.y < 8) {
            // fp16 epilogue via per-warp smem staging (warp-private, syncwarp)
            int rr = lane >> 1, cc = (lane & 1) * 8;
            #pragma unroll
            for (int i = 0; i < 2; i++)
                #pragma unroll
                for (int j = 0; j < 4; j++) {
                    wmma::store_matrix_sync(&st[warp][0][0], acc[i][j], 20,
                                            wmma::mem_row_major);
                    __syncwarp();
                    __half h8[8];
                    #pragma unroll
                    for (int u = 0; u < 8; u++)
                        h8[u] = __float2half(st[warp][rr][cc + u]);
                    *(uint4*)&g_y[(size_t)(row0 + wm * 32 + i * 16 + rr) * 1024
                                  + n0 + wn * 64 + j * 16 + cc] = *(uint4*)h8;
                    __syncwarp();
                }
        } else {
            #pragma unroll
            for (int i = 0; i < 2; i++)
                #pragma unroll
                for (int j = 0; j < 4; j++)
                    wmma::store_matrix_sync(
                        &g_hroot[(size_t)(row0 + wm * 32 + i * 16) * GG
                                 + wn * 64 + j * 16],
                        acc[i][j], GG, wmma::mem_row_major);
        }
    } else {
        int seg = blockIdx.y;
        float* Cb = (seg == 0) ? g_q : (seg == 1) ? g_k : (seg == 2) ? g_v : g_s;
        #pragma unroll
        for (int i = 0; i < 2; i++)
            #pragma unroll
            for (int j = 0; j < 4; j++)
                wmma::store_matrix_sync(
                    &Cb[(size_t)(row0 + wm * 32 + i * 16) * GG + wn * 64 + j * 16],
                    acc[i][j], GG, wmma::mem_row_major);
    }
}

// ---------------- RGCN aggregation: warp per dst, register accumulation -----
__global__ void __launch_bounds__(256)
rgcn_agg_kernel(const int* __restrict__ src,
                const int* __restrict__ et,
                const float* __restrict__ bias) {
    __shared__ float sh_inv[8][8];
    int warp = threadIdx.x >> 5;
    int lane = threadIdx.x & 31;
    int node = blockIdx.x * 8 + warp;
    if (node >= NN) return;
    int beg = g_off[node], end = g_off[node + 1];

    // pass 1: counts per relation (uniform across warp; 8-bit packed)
    unsigned cp0 = 0, cp1 = 0;
    for (int i = beg; i < end; i++) {
        int e = __ldg(&g_eid[i]);
        int r = __ldg(&et[e]);
        if (r < 4) cp0 += 1u << (r * 8);
        else       cp1 += 1u << ((r - 4) * 8);
    }
    if (lane < 8) {
        unsigned c = (lane < 4) ? ((cp0 >> (lane * 8)) & 255u)
                                : ((cp1 >> ((lane - 4) * 8)) & 255u);
        sh_inv[warp][lane] = 1.0f / fmaxf((float)c, 1.0f);
    }
    __syncwarp();

    // pass 2: fp16 gathers (8B per lane per edge) + fp32 accumulate
    float4 a = make_float4(0.f, 0.f, 0.f, 0.f);
    for (int i = beg; i < end; i++) {
        int e = __ldg(&g_eid[i]);
        int s = __ldg(&src[e]);
        int r = __ldg(&et[e]);
        float inv = sh_inv[warp][r];
        uint2 raw = *(const uint2*)&g_y[(size_t)s * 1024 + r * 128 + lane * 4];
        float2 f0 = __half22float2(*(__half2*)&raw.x);
        float2 f1 = __half22float2(*(__half2*)&raw.y);
        a.x += f0.x * inv; a.y += f0.y * inv;
        a.z += f1.x * inv; a.w += f1.y * inv;
    }

    int c0 = lane * 4;
    const float* hr = &g_hroot[(size_t)node * GG + c0];
    float h0 = fmaxf(a.x + hr[0] + bias[c0 + 0], 0.f);
    float h1 = fmaxf(a.y + hr[1] + bias[c0 + 1], 0.f);
    float h2 = fmaxf(a.z + hr[2] + bias[c0 + 2], 0.f);
    float h3 = fmaxf(a.w + hr[3] + bias[c0 + 3], 0.f);
    __nv_bfloat16* row = &g_split[(size_t)node * KSPLIT];
    split_write(row, c0 + 0, h0);
    split_write(row, c0 + 1, h1);
    split_write(row, c0 + 2, h2);
    split_write(row, c0 + 3, h3);
}

// ---------------- attention: warp per dst, register num/den -----------------
__global__ void __launch_bounds__(256)
edge_attn_kernel(const int* __restrict__ src,
                 const float* __restrict__ bq,
                 const float* __restrict__ bk,
                 const float* __restrict__ bv,
                 const float* __restrict__ bs,
                 float* __restrict__ out) {
    int warp = threadIdx.x >> 5;
    int lane = threadIdx.x & 31;
    int node = blockIdx.x * 8 + warp;
    if (node >= NN) return;
    int beg = g_off[node], end = g_off[node + 1];
    int c0 = lane * 4;

    float4 bq4 = *(const float4*)&bq[c0];
    float4 bk4 = *(const float4*)&bk[c0];
    float4 bv4 = *(const float4*)&bv[c0];
    float4 q4 = *(const float4*)&g_q[(size_t)node * GG + c0];
    q4.x += bq4.x; q4.y += bq4.y; q4.z += bq4.z; q4.w += bq4.w;

    float4 num = make_float4(0.f, 0.f, 0.f, 0.f);
    float den = 0.f;
    for (int i = beg; i < end; i++) {
        int e = __ldg(&g_eid[i]);
        int s = __ldg(&src[e]);
        float4 k4 = *(const float4*)&g_k[(size_t)s * GG + c0];
        float d = q4.x * (k4.x + bk4.x) + q4.y * (k4.y + bk4.y)
                + q4.z * (k4.z + bk4.z) + q4.w * (k4.w + bk4.w);
        #pragma unroll
        for (int o = 16; o; o >>= 1) d += __shfl_xor_sync(0xFFFFFFFFu, d, o);
        float ex = __expf(d * 0.08838834764831845f);  // 1/sqrt(128)
        den += ex;
        float4 v4 = *(const float4*)&g_v[(size_t)s * GG + c0];
        num.x += ex * (v4.x + bv4.x);
        num.y += ex * (v4.y + bv4.y);
        num.z += ex * (v4.z + bv4.z);
        num.w += ex * (v4.w + bv4.w);
    }
    float invden = 1.0f / fmaxf(den, 1e-16f);
    const float* sp = &g_s[(size_t)node * GG + c0];
    float4 bs4 = *(const float4*)&bs[c0];
    float4 o4;
    o4.x = fmaxf(num.x * invden + sp[0] + bs4.x, 0.f);
    o4.y = fmaxf(num.y * invden + sp[1] + bs4.y, 0.f);
    o4.z = fmaxf(num.z * invden + sp[2] + bs4.z, 0.f);
    o4.w = fmaxf(num.w * invden + sp[3] + bs4.w, 0.f);
    *(float4*)&out[(size_t)node * GG + c0] = o4;
}

// ---------------------------------------------------------------------------
extern "C" void kernel_launch(void* const* d_in, const int* in_sizes, int n_in,
                              void* d_out, int out_size) {
    const float* x        = (const float*)d_in[0];
    const int* edge_index = (const int*)d_in[1];   // [2, E]: src then dst
    const int* etype      = (const int*)d_in[2];
    const float* rgcn_w   = (const float*)d_in[3];
    const float* rgcn_root= (const float*)d_in[4];
    const float* rgcn_b   = (const float*)d_in[5];
    const float* Wq = (const float*)d_in[6];  const float* bq = (const float*)d_in[7];
    const float* Wk = (const float*)d_in[8];  const float* bk = (const float*)d_in[9];
    const float* Wv = (const float*)d_in[10]; const float* bv = (const float*)d_in[11];
    const float* Ws = (const float*)d_in[12]; const float* bs = (const float*)d_in[13];
    float* out = (float*)d_out;

    const int* src = edge_index;
    const int* dst = edge_index + EE;

    // 0-2: packs + split
    pack_b1_kernel<<<(NOUT1 * GG + 255) / 256, 256>>>(rgcn_w, rgcn_root);
    pack_b2_kernel<<<(NOUT2 * GG + 255) / 256, 256>>>(Wq, Wk, Wv, Ws);
    split_x_kernel<<<(NN * GG + 255) / 256, 256>>>(x);
    // 3 (ncu capture slot): y = x @ [W_r | root]
    {
        dim3 g(NPAD / 128, 9);
        gemm_wmma_kernel<<<g, 256>>>(0);
    }
    // 4-9: CSR build
    init_kernel<<<(NN + 255) / 256, 256>>>();
    deg_kernel<<<(EE + 255) / 256, 256>>>(dst);
    scan1_kernel<<<NB, 256>>>();
    scan2_kernel<<<1, 32>>>();
    scan3_kernel<<<(NN + 255) / 256, 256>>>();
    fill_kernel<<<(EE + 255) / 256, 256>>>(dst);
    // 10: RGCN aggregation (warp/dst, fp16 gathers, register acc) -> g_split
    rgcn_agg_kernel<<<(NN + 7) / 8, 256>>>(src, etype, rgcn_b);
    // 11: q,k,v,skip = h @ [Wq|Wk|Wv|Ws]
    {
        dim3 g(NPAD / 128, 4);
        gemm_wmma_kernel<<<g, 256>>>(1);
    }
    // 12: attention (warp/dst, register num/den) -> out (final)
    edge_attn_kernel<<<(NN + 7) / 8, 256>>>(src, bq, bk, bv, bs, out);
}

// round 17
// speedup vs baseline: 1.4668x; 1.1546x over previous
#include <cuda_runtime.h>
#include <cuda_bf16.h>
#include <cuda_fp16.h>
#include <mma.h>
#include <math.h>
#include <stdint.h>

using namespace nvcuda;

// Problem constants
#define NN 20000
#define NPAD 20096            // 157 * 128 padded M (padding rows never consumed)
#define EE 640000
#define GG 128
#define RR 8
#define KSPLIT 384            // [hi | hi | lo] split-K
#define NOUT1 1152
#define NOUT2 512
#define NB 79                 // ceil(NN/256) scan blocks

// ---------------- scratch (device globals; device-code use only) -----------
__device__ __half g_y[(size_t)NPAD * 1024];              // ~41 MB (relations, fp16)
__device__ float g_hroot[(size_t)NPAD * GG];             // x @ root
__device__ __nv_bfloat16 g_split[(size_t)NPAD * KSPLIT]; // A' (x, later h)
__device__ __nv_bfloat16 g_b1[(size_t)NOUT1 * KSPLIT];
__device__ __nv_bfloat16 g_b2[(size_t)NOUT2 * KSPLIT];
__device__ float g_q[(size_t)NPAD * GG];                 // fp32
__device__ __half g_kh[(size_t)NPAD * GG];               // fp16
__device__ __half g_vh[(size_t)NPAD * GG];               // fp16
__device__ float g_s[(size_t)NPAD * GG];                 // fp32
__device__ int g_deg[NN];
__device__ int g_cur[NN];
__device__ int g_off[NN + 1];
__device__ int g_bsum[NB];
__device__ int g_eid[EE];                                // packed: et<<16 | src

// ---------------- CSR build -------------------------------------------------
__global__ void init_kernel() {
    int i = blockIdx.x * blockDim.x + threadIdx.x;
    if (i < NN) { g_deg[i] = 0; g_cur[i] = 0; }
}

__global__ void deg_kernel(const int* __restrict__ dst) {
    int e = blockIdx.x * blockDim.x + threadIdx.x;
    if (e < EE) atomicAdd(&g_deg[dst[e]], 1);
}

__global__ void scan1_kernel() {
    __shared__ int sh[256];
    int tid = threadIdx.x;
    int i = blockIdx.x * 256 + tid;
    sh[tid] = (i < NN) ? g_deg[i] : 0;
    __syncthreads();
    #pragma unroll
    for (int o = 1; o < 256; o <<= 1) {
        int t = (tid >= o) ? sh[tid - o] : 0;
        __syncthreads();
        sh[tid] += t;
        __syncthreads();
    }
    if (i < NN) g_off[i + 1] = sh[tid];
    if (tid == 255) g_bsum[blockIdx.x] = sh[255];
}

// warp-parallel exclusive scan over NB block sums
__global__ void scan2_kernel() {
    int lane = threadIdx.x;
    int carry = 0;
    for (int base = 0; base < NB; base += 32) {
        int i = base + lane;
        int orig = (i < NB) ? g_bsum[i] : 0;
        int v = orig;
        #pragma unroll
        for (int o = 1; o < 32; o <<= 1) {
            int t = __shfl_up_sync(0xFFFFFFFFu, v, o);
            if (lane >= o) v += t;
        }
        if (i < NB) g_bsum[i] = carry + v - orig;   // exclusive prefix
        carry += __shfl_sync(0xFFFFFFFFu, v, 31);
    }
    if (lane == 0) g_off[0] = 0;
}

__global__ void scan3_kernel() {
    int i = blockIdx.x * blockDim.x + threadIdx.x;
    if (i < NN) g_off[i + 1] += g_bsum[i >> 8];
}

// fill stores a packed record (et<<16 | src): downstream kernels read ONE
// sequential stream instead of two extra random sector gathers per edge.
__global__ void fill_kernel(const int* __restrict__ src,
                            const int* __restrict__ dst,
                            const int* __restrict__ etype) {
    int e = blockIdx.x * blockDim.x + threadIdx.x;
    if (e >= EE) return;
    int d = dst[e];
    int p = atomicAdd(&g_cur[d], 1);
    g_eid[g_off[d] + p] = (etype[e] << 16) | src[e];
}

// ---------------- split packing ---------------------------------------------
__device__ __forceinline__ void split_write(__nv_bfloat16* row, int k, float v) {
    __nv_bfloat16 hi = __float2bfloat16(v);
    __nv_bfloat16 lo = __float2bfloat16(v - __bfloat162float(hi));
    row[k] = hi; row[GG + k] = hi; row[2 * GG + k] = lo;   // A-style [hi|hi|lo]
}
__device__ __forceinline__ void split_write_b(__nv_bfloat16* row, int k, float v) {
    __nv_bfloat16 hi = __float2bfloat16(v);
    __nv_bfloat16 lo = __float2bfloat16(v - __bfloat162float(hi));
    row[k] = hi; row[GG + k] = lo; row[2 * GG + k] = hi;   // B-style [hi|lo|hi]
}

__global__ void pack_b1_kernel(const float* __restrict__ rgcn_w,
                               const float* __restrict__ root) {
    int i = blockIdx.x * blockDim.x + threadIdx.x;
    if (i >= NOUT1 * GG) return;
    int np = i >> 7, k = i & 127;
    float v;
    if (np < 1024) {
        int r = np >> 7, n = np & 127;
        v = rgcn_w[r * 16384 + k * 128 + n];
    } else {
        v = root[k * 128 + (np - 1024)];
    }
    split_write_b(&g_b1[(size_t)np * KSPLIT], k, v);
}

__global__ void pack_b2_kernel(const float* __restrict__ Wq,
                               const float* __restrict__ Wk,
                               const float* __restrict__ Wv,
                               const float* __restrict__ Ws) {
    int i = blockIdx.x * blockDim.x + threadIdx.x;
    if (i >= NOUT2 * GG) return;
    int np = i >> 7, k = i & 127;
    int sel = np >> 7, n = np & 127;
    const float* W = (sel == 0) ? Wq : (sel == 1) ? Wk : (sel == 2) ? Wv : Ws;
    split_write_b(&g_b2[(size_t)np * KSPLIT], k, W[k * 128 + n]);
}

__global__ void split_x_kernel(const float* __restrict__ x) {
    int i = blockIdx.x * blockDim.x + threadIdx.x;
    if (i >= NN * GG) return;
    int m = i >> 7, k = i & 127;
    split_write(&g_split[(size_t)m * KSPLIT], k, x[i]);
}

// ---------------- WMMA bf16 GEMM: 128x128 block tile, BK=32 (proven R8) -----
// fp16 outputs (y, k, v) go through a per-warp smem staging slab (ldm=20,
// multiple of 4 as WMMA requires for float accumulators).
__global__ void __launch_bounds__(256)
gemm_wmma_kernel(int mode) {
    __shared__ __nv_bfloat16 As[128][40];
    __shared__ __nv_bfloat16 Bs[128][40];
    __shared__ float st[8][16][20];    // per-warp 16x16 staging, pitch 20
    int tid = threadIdx.x;
    int warp = tid >> 5;
    int lane = tid & 31;
    int wm = warp >> 1, wn = warp & 1;
    int row0 = blockIdx.x * 128;
    int n0 = blockIdx.y * 128;
    const __nv_bfloat16* Bgm = (mode == 0) ? g_b1 : g_b2;

    wmma::fragment<wmma::accumulator, 16, 16, 16, float> acc[2][4];
    #pragma unroll
    for (int i = 0; i < 2; i++)
        #pragma unroll
        for (int j = 0; j < 4; j++) wmma::fill_fragment(acc[i][j], 0.f);

    for (int k0 = 0; k0 < KSPLIT; k0 += 32) {
        #pragma unroll
        for (int i = 0; i < 2; i++) {
            int idx = tid + i * 256;
            int r = idx >> 2;
            int kc = (idx & 3) * 8;
            *(uint4*)&As[r][kc] =
                *(const uint4*)&g_split[(size_t)(row0 + r) * KSPLIT + k0 + kc];
            *(uint4*)&Bs[r][kc] =
                *(const uint4*)&Bgm[(size_t)(n0 + r) * KSPLIT + k0 + kc];
        }
        __syncthreads();
        #pragma unroll
        for (int ks = 0; ks < 32; ks += 16) {
            wmma::fragment<wmma::matrix_a, 16, 16, 16, __nv_bfloat16, wmma::row_major> af[2];
            wmma::fragment<wmma::matrix_b, 16, 16, 16, __nv_bfloat16, wmma::col_major> bf[4];
            #pragma unroll
            for (int i = 0; i < 2; i++)
                wmma::load_matrix_sync(af[i], &As[wm * 32 + i * 16][ks], 40);
            #pragma unroll
            for (int j = 0; j < 4; j++)
                wmma::load_matrix_sync(bf[j], &Bs[wn * 64 + j * 16][ks], 40);
            #pragma unroll
            for (int i = 0; i < 2; i++)
                #pragma unroll
                for (int j = 0; j < 4; j++)
                    wmma::mma_sync(acc[i][j], af[i], bf[j], acc[i][j]);
        }
        __syncthreads();
    }

    int rr = lane >> 1, cc = (lane & 1) * 8;
    if (mode == 0) {
        if (blockIdx.y < 8) {
            #pragma unroll
            for (int i = 0; i < 2; i++)
                #pragma unroll
                for (int j = 0; j < 4; j++) {
                    wmma::store_matrix_sync(&st[warp][0][0], acc[i][j], 20,
                                            wmma::mem_row_major);
                    __syncwarp();
                    __half h8[8];
                    #pragma unroll
                    for (int u = 0; u < 8; u++)
                        h8[u] = __float2half(st[warp][rr][cc + u]);
                    *(uint4*)&g_y[(size_t)(row0 + wm * 32 + i * 16 + rr) * 1024
                                  + n0 + wn * 64 + j * 16 + cc] = *(uint4*)h8;
                    __syncwarp();
                }
        } else {
            #pragma unroll
            for (int i = 0; i < 2; i++)
                #pragma unroll
                for (int j = 0; j < 4; j++)
                    wmma::store_matrix_sync(
                        &g_hroot[(size_t)(row0 + wm * 32 + i * 16) * GG
                                 + wn * 64 + j * 16],
                        acc[i][j], GG, wmma::mem_row_major);
        }
    } else {
        int seg = blockIdx.y;
        if (seg == 1 || seg == 2) {
            __half* Ch = (seg == 1) ? g_kh : g_vh;
            #pragma unroll
            for (int i = 0; i < 2; i++)
                #pragma unroll
                for (int j = 0; j < 4; j++) {
                    wmma::store_matrix_sync(&st[warp][0][0], acc[i][j], 20,
                                            wmma::mem_row_major);
                    __syncwarp();
                    __half h8[8];
                    #pragma unroll
                    for (int u = 0; u < 8; u++)
                        h8[u] = __float2half(st[warp][rr][cc + u]);
                    *(uint4*)&Ch[(size_t)(row0 + wm * 32 + i * 16 + rr) * GG
                                 + wn * 64 + j * 16 + cc] = *(uint4*)h8;
                    __syncwarp();
                }
        } else {
            float* Cb = (seg == 0) ? g_q : g_s;
            #pragma unroll
            for (int i = 0; i < 2; i++)
                #pragma unroll
                for (int j = 0; j < 4; j++)
                    wmma::store_matrix_sync(
                        &Cb[(size_t)(row0 + wm * 32 + i * 16) * GG
                            + wn * 64 + j * 16],
                        acc[i][j], GG, wmma::mem_row_major);
        }
    }
}

// ---------------- RGCN aggregation: warp per dst, register accumulation -----
__global__ void __launch_bounds__(256)
rgcn_agg_kernel(const float* __restrict__ bias) {
    __shared__ float sh_inv[8][8];
    int warp = threadIdx.x >> 5;
    int lane = threadIdx.x & 31;
    int node = blockIdx.x * 8 + warp;
    if (node >= NN) return;
    int beg = g_off[node], end = g_off[node + 1];

    // pass 1: counts per relation (uniform across warp; 8-bit packed)
    unsigned cp0 = 0, cp1 = 0;
    for (int i = beg; i < end; i++) {
        int r = __ldg(&g_eid[i]) >> 16;
        if (r < 4) cp0 += 1u << (r * 8);
        else       cp1 += 1u << ((r - 4) * 8);
    }
    if (lane < 8) {
        unsigned c = (lane < 4) ? ((cp0 >> (lane * 8)) & 255u)
                                : ((cp1 >> ((lane - 4) * 8)) & 255u);
        sh_inv[warp][lane] = 1.0f / fmaxf((float)c, 1.0f);
    }
    __syncwarp();

    // pass 2: fp16 gathers (8B per lane per edge) + fp32 accumulate
    float4 a = make_float4(0.f, 0.f, 0.f, 0.f);
    for (int i = beg; i < end; i++) {
        int pk = __ldg(&g_eid[i]);
        int s = pk & 0xFFFF;
        int r = pk >> 16;
        float inv = sh_inv[warp][r];
        uint2 raw = *(const uint2*)&g_y[(size_t)s * 1024 + r * 128 + lane * 4];
        float2 f0 = __half22float2(*(__half2*)&raw.x);
        float2 f1 = __half22float2(*(__half2*)&raw.y);
        a.x += f0.x * inv; a.y += f0.y * inv;
        a.z += f1.x * inv; a.w += f1.y * inv;
    }

    int c0 = lane * 4;
    const float* hr = &g_hroot[(size_t)node * GG + c0];
    float h0 = fmaxf(a.x + hr[0] + bias[c0 + 0], 0.f);
    float h1 = fmaxf(a.y + hr[1] + bias[c0 + 1], 0.f);
    float h2 = fmaxf(a.z + hr[2] + bias[c0 + 2], 0.f);
    float h3 = fmaxf(a.w + hr[3] + bias[c0 + 3], 0.f);
    __nv_bfloat16* row = &g_split[(size_t)node * KSPLIT];
    split_write(row, c0 + 0, h0);
    split_write(row, c0 + 1, h1);
    split_write(row, c0 + 2, h2);
    split_write(row, c0 + 3, h3);
}

// ---------------- attention: warp per dst, register num/den -----------------
// k, v read as fp16 (halved gather bytes); q, skip stay fp32.
__global__ void __launch_bounds__(256)
edge_attn_kernel(const float* __restrict__ bq,
                 const float* __restrict__ bk,
                 const float* __restrict__ bv,
                 const float* __restrict__ bs,
                 float* __restrict__ out) {
    int warp = threadIdx.x >> 5;
    int lane = threadIdx.x & 31;
    int node = blockIdx.x * 8 + warp;
    if (node >= NN) return;
    int beg = g_off[node], end = g_off[node + 1];
    int c0 = lane * 4;

    float4 bk4 = *(const float4*)&bk[c0];
    float4 bv4 = *(const float4*)&bv[c0];
    float4 bq4 = *(const float4*)&bq[c0];
    float4 q4 = *(const float4*)&g_q[(size_t)node * GG + c0];
    q4.x += bq4.x; q4.y += bq4.y; q4.z += bq4.z; q4.w += bq4.w;

    float4 num = make_float4(0.f, 0.f, 0.f, 0.f);
    float den = 0.f;
    for (int i = beg; i < end; i++) {
        int s = __ldg(&g_eid[i]) & 0xFFFF;
        uint2 kraw = *(const uint2*)&g_kh[(size_t)s * GG + c0];
        float2 k0 = __half22float2(*(__half2*)&kraw.x);
        float2 k1 = __half22float2(*(__half2*)&kraw.y);
        float d = q4.x * (k0.x + bk4.x) + q4.y * (k0.y + bk4.y)
                + q4.z * (k1.x + bk4.z) + q4.w * (k1.y + bk4.w);
        #pragma unroll
        for (int o = 16; o; o >>= 1) d += __shfl_xor_sync(0xFFFFFFFFu, d, o);
        float ex = __expf(d * 0.08838834764831845f);  // 1/sqrt(128)
        den += ex;
        uint2 vraw = *(const uint2*)&g_vh[(size_t)s * GG + c0];
        float2 v0 = __half22float2(*(__half2*)&vraw.x);
        float2 v1 = __half22float2(*(__half2*)&vraw.y);
        num.x += ex * (v0.x + bv4.x);
        num.y += ex * (v0.y + bv4.y);
        num.z += ex * (v1.x + bv4.z);
        num.w += ex * (v1.y + bv4.w);
    }
    float invden = 1.0f / fmaxf(den, 1e-16f);
    const float* sp = &g_s[(size_t)node * GG + c0];
    float4 bs4 = *(const float4*)&bs[c0];
    float4 o4;
    o4.x = fmaxf(num.x * invden + sp[0] + bs4.x, 0.f);
    o4.y = fmaxf(num.y * invden + sp[1] + bs4.y, 0.f);
    o4.z = fmaxf(num.z * invden + sp[2] + bs4.z, 0.f);
    o4.w = fmaxf(num.w * invden + sp[3] + bs4.w, 0.f);
    *(float4*)&out[(size_t)node * GG + c0] = o4;
}

// ---------------------------------------------------------------------------
extern "C" void kernel_launch(void* const* d_in, const int* in_sizes, int n_in,
                              void* d_out, int out_size) {
    const float* x        = (const float*)d_in[0];
    const int* edge_index = (const int*)d_in[1];   // [2, E]: src then dst
    const int* etype      = (const int*)d_in[2];
    const float* rgcn_w   = (const float*)d_in[3];
    const float* rgcn_root= (const float*)d_in[4];
    const float* rgcn_b   = (const float*)d_in[5];
    const float* Wq = (const float*)d_in[6];  const float* bq = (const float*)d_in[7];
    const float* Wk = (const float*)d_in[8];  const float* bk = (const float*)d_in[9];
    const float* Wv = (const float*)d_in[10]; const float* bv = (const float*)d_in[11];
    const float* Ws = (const float*)d_in[12]; const float* bs = (const float*)d_in[13];
    float* out = (float*)d_out;

    const int* src = edge_index;
    const int* dst = edge_index + EE;

    // 0-2: packs + split
    pack_b1_kernel<<<(NOUT1 * GG + 255) / 256, 256>>>(rgcn_w, rgcn_root);
    pack_b2_kernel<<<(NOUT2 * GG + 255) / 256, 256>>>(Wq, Wk, Wv, Ws);
    split_x_kernel<<<(NN * GG + 255) / 256, 256>>>(x);
    // 3 (ncu capture slot): y = x @ [W_r | root]
    {
        dim3 g(NPAD / 128, 9);
        gemm_wmma_kernel<<<g, 256>>>(0);
    }
    // 4-9: CSR build (packed src|etype records)
    init_kernel<<<(NN + 255) / 256, 256>>>();
    deg_kernel<<<(EE + 255) / 256, 256>>>(dst);
    scan1_kernel<<<NB, 256>>>();
    scan2_kernel<<<1, 32>>>();
    scan3_kernel<<<(NN + 255) / 256, 256>>>();
    fill_kernel<<<(EE + 255) / 256, 256>>>(src, dst, etype);
    // 10: RGCN aggregation (warp/dst, fp16 gathers, register acc) -> g_split
    rgcn_agg_kernel<<<(NN + 7) / 8, 256>>>(rgcn_b);
    // 11: q,k,v,skip = h @ [Wq|Wk|Wv|Ws]  (k, v stored fp16)
    {
        dim3 g(NPAD / 128, 4);
        gemm_wmma_kernel<<<g, 256>>>(1);
    }
    // 12: attention (warp/dst, fp16 k/v gathers) -> out (final)
    edge_attn_kernel<<<(NN + 7) / 8, 256>>>(bq, bk, bv, bs, out);
}